// round 15
// baseline (speedup 1.0000x reference)
#include <cuda_runtime.h>
#include <math.h>

#define BB 16
#define HH 512
#define WW 512
#define HW (HH*WW)
#define NPIX (BB*HW)
#define WORDS_ROW 16           // 512/32
#define WORDS_IMG (HH*WORDS_ROW)

// morph tiling
#define TR 8
#define HALO 9
#define SR (TR + 2*HALO)       // 26 rows
#define SW (SR*WORDS_ROW)      // 416 words
#define MT 256

// ---------------- scratch (device globals: alloc-free rule) ----------------
static __device__ float    g_gray[NPIX];
static __device__ int      g_hist[BB*32];
static __device__ float    g_thr[BB];
static __device__ unsigned g_nucbits[BB*WORDS_IMG];
static __device__ unsigned g_cellbits[BB*WORDS_IMG];
static __device__ unsigned g_bndbits[BB*WORDS_IMG];
static __device__ float    g_par[13];          // sp(cal_a)[4], cal_b[4], alpha[4], tau
static __device__ float    g_part[BB*256*2];   // per-tile (max, sumexp)

__device__ __forceinline__ float softplusf(float v){
    return fmaxf(v, 0.0f) + log1pf(expf(-fabsf(v)));
}

// ---------------- gray + histogram (float4, per-warp hist) ----------------
__global__ void k_gray_hist(const float* __restrict__ img){
    __shared__ int sh[8][32];
    int t = threadIdx.x;
    int w = t >> 5;
    ((int*)sh)[t] = 0;
    __syncthreads();
    int b = blockIdx.y;
    int p4 = blockIdx.x*blockDim.x + t;
    const float4* imr = (const float4*)(img + (size_t)b*3*HW);
    const float4* img_ = imr + (HW/4);
    const float4* imb = imr + 2*(HW/4);
    float4 r4 = __ldcs(imr + p4);
    float4 g4 = __ldcs(img_ + p4);
    float4 b4 = __ldcs(imb + p4);
    float gr[4];
    gr[0] = 0.5f*(0.299f*r4.x + 0.587f*g4.x + 0.114f*b4.x + 1.0f);
    gr[1] = 0.5f*(0.299f*r4.y + 0.587f*g4.y + 0.114f*b4.y + 1.0f);
    gr[2] = 0.5f*(0.299f*r4.z + 0.587f*g4.z + 0.114f*b4.z + 1.0f);
    gr[3] = 0.5f*(0.299f*r4.w + 0.587f*g4.w + 0.114f*b4.w + 1.0f);
    float4 o;
    #pragma unroll
    for (int j = 0; j < 4; j++){
        gr[j] = fminf(fmaxf(gr[j], 0.0f), 1.0f);
        int idx = (int)(gr[j]*32.0f);
        idx = idx < 0 ? 0 : (idx > 31 ? 31 : idx);
        atomicAdd(&sh[w][idx], 1);
    }
    o.x = gr[0]; o.y = gr[1]; o.z = gr[2]; o.w = gr[3];
    ((float4*)(g_gray + (size_t)b*HW))[p4] = o;
    __syncthreads();
    if (t < 32){
        int acc = 0;
        #pragma unroll
        for (int ww = 0; ww < 8; ww++) acc += sh[ww][t];
        atomicAdd(&g_hist[b*32 + t], acc);
    }
}

// ---------------- Otsu + scalar params (consumes + resets hist) ----------------
__global__ void k_otsu_params(const float* __restrict__ cal_a, const float* __restrict__ cal_b,
                              const float* __restrict__ alpha_logits, const float* __restrict__ tau_p){
    int b = blockIdx.x;
    if (threadIdx.x != 0) return;
    float omega[32], mu[32];
    float denom = (float)HW + 1e-6f;
    float o = 0.0f, m = 0.0f;
    for (int k = 0; k < 32; k++){
        float pk = (float)g_hist[b*32 + k] / denom;
        float xk = (float)k / 31.0f;
        o += pk; m += pk*xk;
        omega[k] = o; mu[k] = m;
    }
    for (int k = 0; k < 32; k++) g_hist[b*32 + k] = 0;
    float mu_t = mu[31];
    float best = -1e30f; int kb = 0;
    for (int k = 0; k < 32; k++){
        float num = mu_t*omega[k] - mu[k];
        float s   = num*num / (omega[k]*(1.0f - omega[k]) + 1e-8f);
        if (s > best){ best = s; kb = k; }
    }
    g_thr[b] = (float)kb / 32.0f;
    if (b == 0){
        float al[4]; float mx = -1e30f;
        for (int c = 0; c < 4; c++){ al[c] = alpha_logits[c]; mx = fmaxf(mx, al[c]); }
        float s = 0.0f;
        for (int c = 0; c < 4; c++){ al[c] = expf(al[c] - mx); s += al[c]; }
        for (int c = 0; c < 4; c++){
            g_par[c]     = softplusf(cal_a[c]);
            g_par[4 + c] = cal_b[c];
            g_par[8 + c] = al[c]/s;
        }
        g_par[12] = 0.2f + softplusf(tau_p[0]);
    }
}

// ---------------- bit-packed morphology (double-buffered, TR=8) ----------------
__device__ __forceinline__ unsigned h_ero(const unsigned* S, int r, int k){
    unsigned w = S[r*WORDS_ROW + k];
    unsigned p = (k > 0)             ? S[r*WORDS_ROW + k - 1] : 0u;
    unsigned n = (k < WORDS_ROW - 1) ? S[r*WORDS_ROW + k + 1] : 0u;
    unsigned L = (w << 1) | ((k > 0)             ? (p >> 31) : 1u);
    unsigned R = (w >> 1) | ((k < WORDS_ROW - 1) ? (n << 31) : 0x80000000u);
    return L & w & R;
}
__device__ __forceinline__ unsigned h_dil(const unsigned* S, int r, int k){
    unsigned w = S[r*WORDS_ROW + k];
    unsigned p = (k > 0)             ? S[r*WORDS_ROW + k - 1] : 0u;
    unsigned n = (k < WORDS_ROW - 1) ? S[r*WORDS_ROW + k + 1] : 0u;
    unsigned L = (w << 1) | (p >> 31);
    unsigned R = (w >> 1) | (n << 31);
    return L | w | R;
}
__device__ __forceinline__ unsigned erode3T(const unsigned* S, int r, int k, int gy){
    unsigned v = h_ero(S, r, k);
    if (gy > 0     && r > 0)      v &= h_ero(S, r-1, k);
    if (gy < HH-1  && r < SR-1)   v &= h_ero(S, r+1, k);
    return v;
}
__device__ __forceinline__ unsigned dilate3T(const unsigned* S, int r, int k, int gy){
    unsigned v = h_dil(S, r, k);
    if (gy > 0     && r > 0)      v |= h_dil(S, r-1, k);
    if (gy < HH-1  && r < SR-1)   v |= h_dil(S, r+1, k);
    return v;
}

#define MORPH_STEP2(FN, src, dst)                                   \
    {                                                               \
        _Pragma("unroll")                                           \
        for (int s = 0; s < 2; s++){                                \
            int idx = tid + s*MT;                                   \
            if (idx < SW){                                          \
                int r = idx >> 4, k = idx & 15;                     \
                (dst)[idx] = FN((src), r, k, ty0 - HALO + r);       \
            }                                                       \
        }                                                           \
        __syncthreads();                                            \
    }

__global__ void __launch_bounds__(MT) k_morph(){
    __shared__ unsigned S0[SW];
    __shared__ unsigned S1[SW];
    int b   = blockIdx.y;
    int ty0 = blockIdx.x*TR;
    int tid = threadIdx.x;
    float thr = g_thr[b];
    const float* g = g_gray + (size_t)b*HW;

    #pragma unroll
    for (int s = 0; s < 2; s++){
        int idx = tid + s*MT;
        if (idx < SW){
            int r = idx >> 4, k = idx & 15;
            int gy = ty0 - HALO + r;
            unsigned w = 0;
            if (gy >= 0 && gy < HH){
                const float4* row = (const float4*)(g + gy*WW + k*32);
                #pragma unroll
                for (int j = 0; j < 8; j++){
                    float4 v4 = row[j];
                    w |= (v4.x <= thr ? 1u : 0u) << (4*j);
                    w |= (v4.y <= thr ? 1u : 0u) << (4*j+1);
                    w |= (v4.z <= thr ? 1u : 0u) << (4*j+2);
                    w |= (v4.w <= thr ? 1u : 0u) << (4*j+3);
                }
            }
            S0[idx] = w;
        }
    }
    __syncthreads();

    MORPH_STEP2(erode3T,  S0, S1)
    MORPH_STEP2(dilate3T, S1, S0)
    MORPH_STEP2(dilate3T, S0, S1)
    MORPH_STEP2(erode3T,  S1, S0)   // S0 = nuc, valid rows [4, SR-5]

    // nuc + bnd for center rows (TR*16 = 128 words)
    if (tid < TR*WORDS_ROW){
        int idx = tid;
        int r = (idx >> 4) + HALO, k = idx & 15;
        int gy = ty0 - HALO + r;
        unsigned nu = S0[r*WORDS_ROW + k];
        unsigned er = erode3T(S0, r, k, gy);
        g_nucbits[b*WORDS_IMG + gy*WORDS_ROW + k] = nu;
        g_bndbits[b*WORDS_IMG + gy*WORDS_ROW + k] = nu & ~er;
    }
    // rowmax11: S0 -> S1
    #pragma unroll
    for (int s = 0; s < 2; s++){
        int idx = tid + s*MT;
        if (idx < SW){
            int r = idx >> 4, k = idx & 15;
            unsigned w = S0[r*WORDS_ROW + k];
            unsigned p = (k > 0)             ? S0[r*WORDS_ROW + k - 1] : 0u;
            unsigned n = (k < WORDS_ROW - 1) ? S0[r*WORDS_ROW + k + 1] : 0u;
            unsigned long long lo = ((unsigned long long)w << 32) | p;
            unsigned long long hi = ((unsigned long long)n << 32) | w;
            unsigned v = w;
            #pragma unroll
            for (int sh = 1; sh <= 5; sh++){
                v |= (unsigned)(lo >> (32 - sh));
                v |= (unsigned)(hi >> sh);
            }
            S1[idx] = v;
        }
    }
    __syncthreads();
    // colmax11 -> cell bits for center rows
    if (tid < TR*WORDS_ROW){
        int idx = tid;
        int r = (idx >> 4) + HALO, k = idx & 15;
        int gy = ty0 - HALO + r;
        int d0 = (gy - 5 < 0)    ? -gy          : -5;
        int d1 = (gy + 5 > HH-1) ? (HH-1 - gy)  :  5;
        unsigned v = 0;
        for (int d = d0; d <= d1; d++) v |= S1[(r + d)*WORDS_ROW + k];
        g_cellbits[b*WORDS_IMG + gy*WORDS_ROW + k] = v;
    }
}

// ---------------- fused maps kernel (2x2 quad, interior/boundary paths) ----------------
__device__ __forceinline__ unsigned winN(const unsigned* w3, int rel, int width){
    unsigned long long c = ((unsigned long long)w3[1] << 32) | (unsigned long long)w3[0];
    unsigned long long v = c >> rel;
    if (rel + width > 64) v |= ((unsigned long long)w3[2]) << (64 - rel);
    return (unsigned)v & ((1u << width) - 1u);
}

__device__ __forceinline__ void hsum2(const float* P, int yi, int xi0, float& s0, float& s1){
    const float* row = P + yi*40 + xi0;
    float t0 = row[0];
    float s = t0 + row[1] + row[2] + row[3] + row[4]
                 + row[5] + row[6] + row[7] + row[8];
    s0 = s;
    s1 = s - t0 + row[9];
}

__device__ __forceinline__ void maps_pixel(
    float invden,
    float s_sn, float s_cs, float s_g, float s_g2,
    int an, int csum, float lap, unsigned bc, int bs,
    float& rough, float& circ, float& ncv, float& ent, float& E)
{
    float ms = s_sn*invden, mc = s_cs*invden;
    float t = ms*ms + mc*mc + 1e-6f;
    circ = 1.0f - t*rsqrtf(t);
    float g1 = s_g*invden, g2v = s_g2*invden;
    ent = __logf(1.0f + fmaxf(g2v - g1*g1, 0.0f));
    float A_c = fmaxf((float)(csum - an), 1.0f);
    ncv = __fdividef((float)an, A_c);
    rough = lap*(float)bc*__fdividef(1.0f, (float)bs + 1e-6f);

    float z0s = __logf(1.0f + rough);
    float z1s = fminf(fmaxf(circ, 0.0f), 1.0f);
    float z2s = __logf(1.0f + ncv);
    float z3s = fminf(fmaxf(ent, 0.0f), 3.4657359f);
    E = g_par[8 ]*(g_par[0]*z0s + g_par[4])
      + g_par[9 ]*(g_par[1]*z1s + g_par[5])
      + g_par[10]*(g_par[2]*z2s + g_par[6])
      + g_par[11]*(g_par[3]*z3s + g_par[7]);
}

__device__ __forceinline__ float bnd_invden(int gx, int gy){
    int rows_in = ((gy+4 > HH-1 ? HH-1 : gy+4) - (gy-4 < 0 ? 0 : gy-4) + 1);
    int cols_in = ((gx+4 > WW-1 ? WW-1 : gx+4) - (gx-4 < 0 ? 0 : gx-4) + 1);
    return __fdividef(1.0f, (float)(rows_in*cols_in) + 1e-6f);
}

template<bool INTERIOR>
__device__ __forceinline__ void fused_body(
    float* __restrict__ out, int tx, int ty, int tid, int tx0, int ty0, int b,
    float* sg, float* p0, float* p1, float* vs0, float* vs1,
    unsigned* nucw, unsigned* cellw, unsigned* bndw,
    float& E00, float& E01, float& E10, float& E11)
{
    const float* g = g_gray + (size_t)b*HW;

    for (int idx = tid; idx < 42*42; idx += 256){
        int rr = idx/42, cc = idx%42;
        int gy = ty0 - 5 + rr, gx = tx0 - 5 + cc;
        float v;
        if (INTERIOR){
            v = g[gy*WW + gx];
        } else {
            v = 0.0f;
            if (gy >= 0 && gy < HH && gx >= 0 && gx < WW) v = g[gy*WW + gx];
        }
        sg[rr*43 + cc] = v;
    }
    {
        int kw0 = (tx0 >> 5) - 1;
        for (int idx = tid; idx < 120; idx += 256){
            int r = idx/3, c = idx%3;
            int gy = ty0 - 4 + r;
            int kw = kw0 + c;
            unsigned nv, cv, bv;
            if (INTERIOR){
                int off = b*WORDS_IMG + gy*WORDS_ROW + kw;
                nv = g_nucbits[off]; cv = g_cellbits[off]; bv = g_bndbits[off];
            } else {
                nv = 0; cv = 0; bv = 0;
                if (gy >= 0 && gy < HH && kw >= 0 && kw < WORDS_ROW){
                    int off = b*WORDS_IMG + gy*WORDS_ROW + kw;
                    nv = g_nucbits[off]; cv = g_cellbits[off]; bv = g_bndbits[off];
                }
            }
            nucw[idx] = nv; cellw[idx] = cv; bndw[idx] = bv;
        }
    }
    __syncthreads();

    // stage1: sobel -> unit vector on 40x40 halo
    for (int idx = tid; idx < 40*40; idx += 256){
        int r = idx/40, c = idx%40;
        float sn = 0.0f, cs = 1.0f;
        bool inb = true;
        if (!INTERIOR){
            int gy = ty0 - 4 + r, gx = tx0 - 4 + c;
            inb = (gy >= 0 && gy < HH && gx >= 0 && gx < WW);
        }
        if (inb){
            const float* p = sg + r*43 + c;
            float v00 = p[0],  v01 = p[1],  v02 = p[2];
            float v10 = p[43],              v12 = p[45];
            float v20 = p[86], v21 = p[87], v22 = p[88];
            float gxv = (v00 + 2.0f*v10 + v20) - (v02 + 2.0f*v12 + v22);
            float gyv = (v00 + 2.0f*v01 + v02) - (v20 + 2.0f*v21 + v22);
            float r2 = gxv*gxv + gyv*gyv;
            if (r2 > 0.0f){
                float inv = rsqrtf(r2);
                sn = gyv*inv; cs = gxv*inv;
            } else { sn = 0.0f; cs = 1.0f; }
        } else { sn = 0.0f; cs = 0.0f; }
        p0[idx] = sn; p1[idx] = cs;
    }
    __syncthreads();

    // stage2a: vertical 9-sums of sin/cos, row-pair incremental
    for (int idx = tid; idx < 16*40; idx += 256){
        int pr = idx/40, j = idx - pr*40;
        int y0 = 2*pr;
        float a0 = 0.0f, b0 = 0.0f;
        #pragma unroll
        for (int k = 0; k < 9; k++){
            a0 += p0[(y0+k)*40 + j];
            b0 += p1[(y0+k)*40 + j];
        }
        float a1 = a0 - p0[y0*40 + j] + p0[(y0+9)*40 + j];
        float b1 = b0 - p1[y0*40 + j] + p1[(y0+9)*40 + j];
        vs0[y0*40 + j] = a0; vs0[(y0+1)*40 + j] = a1;
        vs1[y0*40 + j] = b0; vs1[(y0+1)*40 + j] = b1;
    }
    __syncthreads();

    // stage2b: vertical 9-sums of gray/gray^2 into reused p0/p1
    for (int idx = tid; idx < 16*40; idx += 256){
        int pr = idx/40, j = idx - pr*40;
        int y0 = 2*pr;
        float c0 = 0.0f, d0 = 0.0f;
        #pragma unroll
        for (int k = 0; k < 9; k++){
            float gv = sg[(y0+1+k)*43 + (j+1)];
            c0 += gv;
            d0 += gv*gv;
        }
        float gold = sg[(y0+1)*43 + (j+1)];
        float gnew = sg[(y0+10)*43 + (j+1)];
        float c1 = c0 - gold + gnew;
        float d1 = d0 - gold*gold + gnew*gnew;
        p0[y0*40 + j] = c0; p0[(y0+1)*40 + j] = c1;
        p1[y0*40 + j] = d0; p1[(y0+1)*40 + j] = d1;
    }
    __syncthreads();

    // stage3: 2x2 quad per thread
    int xi0 = 2*tx;
    int yi0 = 2*ty, yi1 = yi0 + 1;
    int gx0 = tx0 + xi0;
    int gy0 = ty0 + yi0, gy1 = gy0 + 1;

    int anA = 0, anB = 0, csA = 0, csB = 0;
    #pragma unroll
    for (int k = 0; k < 10; k++){
        unsigned wn = winN(&nucw[(yi0+k)*3],  xi0 + 28, 10);
        unsigned wc = winN(&cellw[(yi0+k)*3], xi0 + 28, 10);
        int pn = __popc(wn)*0x10001 - (int)((wn >> 9) & 1u) - (int)((wn & 1u) << 16);
        int pc = __popc(wc)*0x10001 - (int)((wc >> 9) & 1u) - (int)((wc & 1u) << 16);
        if (k < 9){ anA += pn; csA += pc; }
        if (k > 0){ anB += pn; csB += pc; }
    }
    int bsA = 0, bsB = 0;
    #pragma unroll
    for (int k = 0; k < 6; k++){
        unsigned wb = winN(&bndw[(yi0+2+k)*3], xi0 + 30, 6);
        int pb = __popc(wb)*0x10001 - (int)((wb >> 5) & 1u) - (int)((wb & 1u) << 16);
        if (k < 5) bsA += pb;
        if (k > 0) bsB += pb;
    }

    unsigned wA = winN(&nucw[(yi0+3)*3], xi0 + 32, 2);
    unsigned wB = winN(&nucw[(yi0+4)*3], xi0 + 31, 4);
    unsigned wC = winN(&nucw[(yi0+5)*3], xi0 + 31, 4);
    unsigned wD = winN(&nucw[(yi0+6)*3], xi0 + 32, 2);
    unsigned bBv = winN(&bndw[(yi0+4)*3], xi0 + 32, 2);
    unsigned bCv = winN(&bndw[(yi0+5)*3], xi0 + 32, 2);

    unsigned a0b = wA & 1u,        a1b = (wA >> 1) & 1u;
    unsigned b0b = wB & 1u,        b1b = (wB >> 1) & 1u, b2b = (wB >> 2) & 1u, b3b = (wB >> 3) & 1u;
    unsigned c0b = wC & 1u,        c1b = (wC >> 1) & 1u, c2b = (wC >> 2) & 1u, c3b = (wC >> 3) & 1u;
    unsigned d0b = wD & 1u,        d1b = (wD >> 1) & 1u;

    float lap00 = fabsf((float)(a0b + c1b + b0b + b2b) - 4.0f*(float)b1b);
    float lap01 = fabsf((float)(a1b + c2b + b1b + b3b) - 4.0f*(float)b2b);
    float lap10 = fabsf((float)(b1b + d0b + c0b + c2b) - 4.0f*(float)c1b);
    float lap11 = fabsf((float)(b2b + d1b + c1b + c3b) - 4.0f*(float)c2b);

    const float INV81 = 1.0f/(81.0f + 1e-6f);

    float* zbase = out + (size_t)NPIX + (size_t)b*4*HW;
    float* nbase = out + 5*(size_t)NPIX + (size_t)b*HW;
    float* ebase = out + 6*(size_t)NPIX + (size_t)b*HW;

    // --- row y0 ---
    {
        float a0, a1, q0, q1, c0, c1, d0, d1;
        hsum2(vs0, yi0, xi0, a0, a1);
        hsum2(vs1, yi0, xi0, q0, q1);
        hsum2(p0,  yi0, xi0, c0, c1);
        hsum2(p1,  yi0, xi0, d0, d1);
        float inv0 = INTERIOR ? INV81 : bnd_invden(gx0,   gy0);
        float inv1 = INTERIOR ? INV81 : bnd_invden(gx0+1, gy0);
        float r0, ci0, n0, e0, r1, ci1, n1, e1;
        maps_pixel(inv0, a0, q0, c0, d0, anA & 0xFFFF, csA & 0xFFFF,
                   lap00, bBv & 1u, bsA & 0xFFFF, r0, ci0, n0, e0, E00);
        maps_pixel(inv1, a1, q1, c1, d1, anA >> 16, csA >> 16,
                   lap01, (bBv >> 1) & 1u, bsA >> 16, r1, ci1, n1, e1, E01);
        size_t pix = (size_t)gy0*WW + gx0;
        __stcs((float2*)(zbase + pix),        make_float2(r0, r1));
        __stcs((float2*)(zbase + HW + pix),   make_float2(ci0, ci1));
        __stcs((float2*)(zbase + 2*HW + pix), make_float2(n0, n1));
        __stcs((float2*)(zbase + 3*HW + pix), make_float2(e0, e1));
        __stcs((float2*)(nbase + pix),        make_float2((float)b1b, (float)b2b));
        *(float2*)(ebase + pix) = make_float2(E00, E01);   // re-read by k_A
    }
    // --- row y1 ---
    {
        float a0, a1, q0, q1, c0, c1, d0, d1;
        hsum2(vs0, yi1, xi0, a0, a1);
        hsum2(vs1, yi1, xi0, q0, q1);
        hsum2(p0,  yi1, xi0, c0, c1);
        hsum2(p1,  yi1, xi0, d0, d1);
        float inv0 = INTERIOR ? INV81 : bnd_invden(gx0,   gy1);
        float inv1 = INTERIOR ? INV81 : bnd_invden(gx0+1, gy1);
        float r0, ci0, n0, e0, r1, ci1, n1, e1;
        maps_pixel(inv0, a0, q0, c0, d0, anB & 0xFFFF, csB & 0xFFFF,
                   lap10, bCv & 1u, bsB & 0xFFFF, r0, ci0, n0, e0, E10);
        maps_pixel(inv1, a1, q1, c1, d1, anB >> 16, csB >> 16,
                   lap11, (bCv >> 1) & 1u, bsB >> 16, r1, ci1, n1, e1, E11);
        size_t pix = (size_t)gy1*WW + gx0;
        __stcs((float2*)(zbase + pix),        make_float2(r0, r1));
        __stcs((float2*)(zbase + HW + pix),   make_float2(ci0, ci1));
        __stcs((float2*)(zbase + 2*HW + pix), make_float2(n0, n1));
        __stcs((float2*)(zbase + 3*HW + pix), make_float2(e0, e1));
        __stcs((float2*)(nbase + pix),        make_float2((float)c1b, (float)c2b));
        *(float2*)(ebase + pix) = make_float2(E10, E11);
    }
}

__global__ void __launch_bounds__(256, 5) k_fused(float* __restrict__ out){
    __shared__ float sg[42*43];
    __shared__ float p0[40*40];
    __shared__ float p1[40*40];
    __shared__ float vs0[32*40], vs1[32*40];
    __shared__ unsigned nucw[40*3], cellw[40*3], bndw[40*3];
    __shared__ float wred[8];

    int tx = threadIdx.x, ty = threadIdx.y;   // 16 x 16
    int tid = ty*16 + tx;
    int tx0 = blockIdx.x*32, ty0 = blockIdx.y*32;
    int b = blockIdx.z;

    bool interior = (blockIdx.x > 0) && (blockIdx.x < 15) && (blockIdx.y > 0) && (blockIdx.y < 15);

    float E00, E01, E10, E11;
    if (interior)
        fused_body<true >(out, tx, ty, tid, tx0, ty0, b, sg, p0, p1, vs0, vs1, nucw, cellw, bndw, E00, E01, E10, E11);
    else
        fused_body<false>(out, tx, ty, tid, tx0, ty0, b, sg, p0, p1, vs0, vs1, nucw, cellw, bndw, E00, E01, E10, E11);

    // softmax partials (8 warps)
    int lane = tid & 31, wid = tid >> 5;
    float invtau = __fdividef(1.0f, g_par[12]);
    float z00 = -E00*invtau, z01 = -E01*invtau, z10 = -E10*invtau, z11 = -E11*invtau;
    float m = fmaxf(fmaxf(z00, z01), fmaxf(z10, z11));
    #pragma unroll
    for (int o = 16; o > 0; o >>= 1) m = fmaxf(m, __shfl_xor_sync(0xFFFFFFFFu, m, o));
    if (lane == 0) wred[wid] = m;
    __syncthreads();
    if (wid == 0){
        float mm = (lane < 8) ? wred[lane] : -1e30f;
        #pragma unroll
        for (int o = 4; o > 0; o >>= 1) mm = fmaxf(mm, __shfl_xor_sync(0xFFFFFFFFu, mm, o));
        if (lane == 0) wred[0] = mm;
    }
    __syncthreads();
    float M = wred[0];
    float e = __expf(z00 - M) + __expf(z01 - M) + __expf(z10 - M) + __expf(z11 - M);
    #pragma unroll
    for (int o = 16; o > 0; o >>= 1) e += __shfl_xor_sync(0xFFFFFFFFu, e, o);
    __syncthreads();
    if (lane == 0) wred[wid] = e;
    __syncthreads();
    if (wid == 0){
        float ss = (lane < 8) ? wred[lane] : 0.0f;
        #pragma unroll
        for (int o = 4; o > 0; o >>= 1) ss += __shfl_xor_sync(0xFFFFFFFFu, ss, o);
        if (lane == 0){
            int tile = blockIdx.y*16 + blockIdx.x;
            g_part[(b*256 + tile)*2    ] = M;
            g_part[(b*256 + tile)*2 + 1] = ss;
        }
    }
}

// ---------------- final A (512 threads; inlines the partial combine) ----------------
__global__ void __launch_bounds__(512) k_A(float* __restrict__ out){
    __shared__ float wred[16];
    __shared__ float fin[2];
    int b = blockIdx.y;
    int t = threadIdx.x;
    int lane = t & 31, wid = t >> 5;

    float m = -1e30f, s = 0.0f;
    if (t < 256){
        m = g_part[(b*256 + t)*2];
        s = g_part[(b*256 + t)*2 + 1];
    }
    float mm = m;
    #pragma unroll
    for (int o = 16; o > 0; o >>= 1) mm = fmaxf(mm, __shfl_xor_sync(0xFFFFFFFFu, mm, o));
    if (lane == 0 && wid < 8) wred[wid] = mm;
    __syncthreads();
    if (wid == 0){
        float v = (lane < 8) ? wred[lane] : -1e30f;
        #pragma unroll
        for (int o = 4; o > 0; o >>= 1) v = fmaxf(v, __shfl_xor_sync(0xFFFFFFFFu, v, o));
        if (lane == 0) fin[0] = v;
    }
    __syncthreads();
    float M = fin[0];
    float e = (t < 256) ? s*__expf(m - M) : 0.0f;
    #pragma unroll
    for (int o = 16; o > 0; o >>= 1) e += __shfl_xor_sync(0xFFFFFFFFu, e, o);
    __syncthreads();
    if (lane == 0 && wid < 8) wred[wid] = e;
    __syncthreads();
    if (wid == 0){
        float v = (lane < 8) ? wred[lane] : 0.0f;
        #pragma unroll
        for (int o = 4; o > 0; o >>= 1) v += __shfl_xor_sync(0xFFFFFFFFu, v, o);
        if (lane == 0) fin[1] = v;
    }
    __syncthreads();
    float invS = __fdividef(1.0f, fin[1]);
    float invtau = __fdividef(1.0f, g_par[12]);

    int p4 = blockIdx.x*512 + t;
    float4 E4 = ((const float4*)(out + 6*(size_t)NPIX + (size_t)b*HW))[p4];
    float4 A4;
    A4.x = __expf(-E4.x*invtau - M)*invS;
    A4.y = __expf(-E4.y*invtau - M)*invS;
    A4.z = __expf(-E4.z*invtau - M)*invS;
    A4.w = __expf(-E4.w*invtau - M)*invS;
    __stcs((float4*)(out + (size_t)b*HW) + p4, A4);
}

// ---------------- launch ----------------
extern "C" void kernel_launch(void* const* d_in, const int* in_sizes, int n_in,
                              void* d_out, int out_size){
    const float* img    = (const float*)d_in[0];
    const float* cal_a  = (const float*)d_in[1];
    const float* cal_b  = (const float*)d_in[2];
    const float* alpha  = (const float*)d_in[3];
    const float* tau_p  = (const float*)d_in[4];
    float* out = (float*)d_out;
    (void)in_sizes; (void)n_in; (void)out_size;

    k_gray_hist<<<dim3(HW/(256*4), BB, 1), 256>>>(img);
    k_otsu_params<<<BB, 32>>>(cal_a, cal_b, alpha, tau_p);
    k_morph<<<dim3(HH/TR, BB, 1), MT>>>();
    k_fused<<<dim3(16, 16, BB), dim3(16, 16, 1)>>>(out);
    k_A<<<dim3(HW/(512*4), BB, 1), 512>>>(out);
}

// round 16
// speedup vs baseline: 1.0550x; 1.0550x over previous
#include <cuda_runtime.h>
#include <math.h>

#define BB 16
#define HH 512
#define WW 512
#define HW (HH*WW)
#define NPIX (BB*HW)
#define WORDS_ROW 16           // 512/32
#define WORDS_IMG (HH*WORDS_ROW)

// morph tiling (TR=16: best measured config)
#define TR 16
#define HALO 9
#define SR (TR + 2*HALO)       // 34 rows
#define SW (SR*WORDS_ROW)      // 544 words
#define MT 256

// ---------------- scratch (device globals: alloc-free rule) ----------------
static __device__ float    g_gray[NPIX];
static __device__ int      g_hist[BB*32];
static __device__ float    g_thr[BB];
static __device__ unsigned g_nucbits[BB*WORDS_IMG];
static __device__ unsigned g_cellbits[BB*WORDS_IMG];
static __device__ unsigned g_bndbits[BB*WORDS_IMG];
static __device__ float    g_par[13];          // sp(cal_a)[4], cal_b[4], alpha[4], tau
static __device__ float    g_part[BB*256*2];   // per-tile (max, sumexp)

__device__ __forceinline__ float softplusf(float v){
    return fmaxf(v, 0.0f) + log1pf(expf(-fabsf(v)));
}

// ---------------- gray + histogram (float4, per-warp hist) ----------------
__global__ void k_gray_hist(const float* __restrict__ img){
    __shared__ int sh[8][32];
    int t = threadIdx.x;
    int w = t >> 5;
    ((int*)sh)[t] = 0;
    __syncthreads();
    int b = blockIdx.y;
    int p4 = blockIdx.x*blockDim.x + t;
    const float4* imr = (const float4*)(img + (size_t)b*3*HW);
    const float4* img_ = imr + (HW/4);
    const float4* imb = imr + 2*(HW/4);
    float4 r4 = __ldcs(imr + p4);
    float4 g4 = __ldcs(img_ + p4);
    float4 b4 = __ldcs(imb + p4);
    float gr[4];
    gr[0] = 0.5f*(0.299f*r4.x + 0.587f*g4.x + 0.114f*b4.x + 1.0f);
    gr[1] = 0.5f*(0.299f*r4.y + 0.587f*g4.y + 0.114f*b4.y + 1.0f);
    gr[2] = 0.5f*(0.299f*r4.z + 0.587f*g4.z + 0.114f*b4.z + 1.0f);
    gr[3] = 0.5f*(0.299f*r4.w + 0.587f*g4.w + 0.114f*b4.w + 1.0f);
    float4 o;
    #pragma unroll
    for (int j = 0; j < 4; j++){
        gr[j] = fminf(fmaxf(gr[j], 0.0f), 1.0f);
        int idx = (int)(gr[j]*32.0f);
        idx = idx < 0 ? 0 : (idx > 31 ? 31 : idx);
        atomicAdd(&sh[w][idx], 1);
    }
    o.x = gr[0]; o.y = gr[1]; o.z = gr[2]; o.w = gr[3];
    ((float4*)(g_gray + (size_t)b*HW))[p4] = o;
    __syncthreads();
    if (t < 32){
        int acc = 0;
        #pragma unroll
        for (int ww = 0; ww < 8; ww++) acc += sh[ww][t];
        atomicAdd(&g_hist[b*32 + t], acc);
    }
}

// ---------------- Otsu + scalar params (consumes + resets hist) ----------------
__global__ void k_otsu_params(const float* __restrict__ cal_a, const float* __restrict__ cal_b,
                              const float* __restrict__ alpha_logits, const float* __restrict__ tau_p){
    int b = blockIdx.x;
    if (threadIdx.x != 0) return;
    float omega[32], mu[32];
    float denom = (float)HW + 1e-6f;
    float o = 0.0f, m = 0.0f;
    for (int k = 0; k < 32; k++){
        float pk = (float)g_hist[b*32 + k] / denom;
        float xk = (float)k / 31.0f;
        o += pk; m += pk*xk;
        omega[k] = o; mu[k] = m;
    }
    for (int k = 0; k < 32; k++) g_hist[b*32 + k] = 0;
    float mu_t = mu[31];
    float best = -1e30f; int kb = 0;
    for (int k = 0; k < 32; k++){
        float num = mu_t*omega[k] - mu[k];
        float s   = num*num / (omega[k]*(1.0f - omega[k]) + 1e-8f);
        if (s > best){ best = s; kb = k; }
    }
    g_thr[b] = (float)kb / 32.0f;
    if (b == 0){
        float al[4]; float mx = -1e30f;
        for (int c = 0; c < 4; c++){ al[c] = alpha_logits[c]; mx = fmaxf(mx, al[c]); }
        float s = 0.0f;
        for (int c = 0; c < 4; c++){ al[c] = expf(al[c] - mx); s += al[c]; }
        for (int c = 0; c < 4; c++){
            g_par[c]     = softplusf(cal_a[c]);
            g_par[4 + c] = cal_b[c];
            g_par[8 + c] = al[c]/s;
        }
        g_par[12] = 0.2f + softplusf(tau_p[0]);
    }
}

// ---------------- bit-packed morphology (double-buffered, TR=16) ----------------
__device__ __forceinline__ unsigned h_ero(const unsigned* S, int r, int k){
    unsigned w = S[r*WORDS_ROW + k];
    unsigned p = (k > 0)             ? S[r*WORDS_ROW + k - 1] : 0u;
    unsigned n = (k < WORDS_ROW - 1) ? S[r*WORDS_ROW + k + 1] : 0u;
    unsigned L = (w << 1) | ((k > 0)             ? (p >> 31) : 1u);
    unsigned R = (w >> 1) | ((k < WORDS_ROW - 1) ? (n << 31) : 0x80000000u);
    return L & w & R;
}
__device__ __forceinline__ unsigned h_dil(const unsigned* S, int r, int k){
    unsigned w = S[r*WORDS_ROW + k];
    unsigned p = (k > 0)             ? S[r*WORDS_ROW + k - 1] : 0u;
    unsigned n = (k < WORDS_ROW - 1) ? S[r*WORDS_ROW + k + 1] : 0u;
    unsigned L = (w << 1) | (p >> 31);
    unsigned R = (w >> 1) | (n << 31);
    return L | w | R;
}
__device__ __forceinline__ unsigned erode3T(const unsigned* S, int r, int k, int gy){
    unsigned v = h_ero(S, r, k);
    if (gy > 0     && r > 0)      v &= h_ero(S, r-1, k);
    if (gy < HH-1  && r < SR-1)   v &= h_ero(S, r+1, k);
    return v;
}
__device__ __forceinline__ unsigned dilate3T(const unsigned* S, int r, int k, int gy){
    unsigned v = h_dil(S, r, k);
    if (gy > 0     && r > 0)      v |= h_dil(S, r-1, k);
    if (gy < HH-1  && r < SR-1)   v |= h_dil(S, r+1, k);
    return v;
}

#define MORPH_STEP2(FN, src, dst)                                   \
    {                                                               \
        _Pragma("unroll")                                           \
        for (int s = 0; s < 3; s++){                                \
            int idx = tid + s*MT;                                   \
            if (idx < SW){                                          \
                int r = idx >> 4, k = idx & 15;                     \
                (dst)[idx] = FN((src), r, k, ty0 - HALO + r);       \
            }                                                       \
        }                                                           \
        __syncthreads();                                            \
    }

__global__ void __launch_bounds__(MT) k_morph(){
    __shared__ unsigned S0[SW];
    __shared__ unsigned S1[SW];
    int b   = blockIdx.y;
    int ty0 = blockIdx.x*TR;
    int tid = threadIdx.x;
    float thr = g_thr[b];
    const float* g = g_gray + (size_t)b*HW;

    #pragma unroll
    for (int s = 0; s < 3; s++){
        int idx = tid + s*MT;
        if (idx < SW){
            int r = idx >> 4, k = idx & 15;
            int gy = ty0 - HALO + r;
            unsigned w = 0;
            if (gy >= 0 && gy < HH){
                const float4* row = (const float4*)(g + gy*WW + k*32);
                #pragma unroll
                for (int j = 0; j < 8; j++){
                    float4 v4 = row[j];
                    w |= (v4.x <= thr ? 1u : 0u) << (4*j);
                    w |= (v4.y <= thr ? 1u : 0u) << (4*j+1);
                    w |= (v4.z <= thr ? 1u : 0u) << (4*j+2);
                    w |= (v4.w <= thr ? 1u : 0u) << (4*j+3);
                }
            }
            S0[idx] = w;
        }
    }
    __syncthreads();

    MORPH_STEP2(erode3T,  S0, S1)
    MORPH_STEP2(dilate3T, S1, S0)
    MORPH_STEP2(dilate3T, S0, S1)
    MORPH_STEP2(erode3T,  S1, S0)   // S0 = nuc

    {
        int idx = tid;
        int r = (idx >> 4) + HALO, k = idx & 15;
        int gy = ty0 - HALO + r;
        unsigned nu = S0[r*WORDS_ROW + k];
        unsigned er = erode3T(S0, r, k, gy);
        g_nucbits[b*WORDS_IMG + gy*WORDS_ROW + k] = nu;
        g_bndbits[b*WORDS_IMG + gy*WORDS_ROW + k] = nu & ~er;
    }
    #pragma unroll
    for (int s = 0; s < 3; s++){
        int idx = tid + s*MT;
        if (idx < SW){
            int r = idx >> 4, k = idx & 15;
            unsigned w = S0[r*WORDS_ROW + k];
            unsigned p = (k > 0)             ? S0[r*WORDS_ROW + k - 1] : 0u;
            unsigned n = (k < WORDS_ROW - 1) ? S0[r*WORDS_ROW + k + 1] : 0u;
            unsigned long long lo = ((unsigned long long)w << 32) | p;
            unsigned long long hi = ((unsigned long long)n << 32) | w;
            unsigned v = w;
            #pragma unroll
            for (int sh = 1; sh <= 5; sh++){
                v |= (unsigned)(lo >> (32 - sh));
                v |= (unsigned)(hi >> sh);
            }
            S1[idx] = v;
        }
    }
    __syncthreads();
    {
        int idx = tid;
        int r = (idx >> 4) + HALO, k = idx & 15;
        int gy = ty0 - HALO + r;
        int d0 = (gy - 5 < 0)    ? -gy          : -5;
        int d1 = (gy + 5 > HH-1) ? (HH-1 - gy)  :  5;
        unsigned v = 0;
        for (int d = d0; d <= d1; d++) v |= S1[(r + d)*WORDS_ROW + k];
        g_cellbits[b*WORDS_IMG + gy*WORDS_ROW + k] = v;
    }
}

// ---------------- fused maps kernel (2x2 quad, interior/boundary paths) ----------------
__device__ __forceinline__ unsigned winN(const unsigned* w3, int rel, int width){
    unsigned long long c = ((unsigned long long)w3[1] << 32) | (unsigned long long)w3[0];
    unsigned long long v = c >> rel;
    if (rel + width > 64) v |= ((unsigned long long)w3[2]) << (64 - rel);
    return (unsigned)v & ((1u << width) - 1u);
}

__device__ __forceinline__ void hsum2(const float* P, int yi, int xi0, float& s0, float& s1){
    const float* row = P + yi*40 + xi0;
    float t0 = row[0];
    float s = t0 + row[1] + row[2] + row[3] + row[4]
                 + row[5] + row[6] + row[7] + row[8];
    s0 = s;
    s1 = s - t0 + row[9];
}

__device__ __forceinline__ void maps_pixel(
    float invden,
    float s_sn, float s_cs, float s_g, float s_g2,
    int an, int csum, float lap, unsigned bc, int bs,
    float& rough, float& circ, float& ncv, float& ent, float& E)
{
    float ms = s_sn*invden, mc = s_cs*invden;
    float t = ms*ms + mc*mc + 1e-6f;
    circ = 1.0f - t*rsqrtf(t);
    float g1 = s_g*invden, g2v = s_g2*invden;
    ent = __logf(1.0f + fmaxf(g2v - g1*g1, 0.0f));
    float A_c = fmaxf((float)(csum - an), 1.0f);
    ncv = __fdividef((float)an, A_c);
    rough = lap*(float)bc*__fdividef(1.0f, (float)bs + 1e-6f);

    float z0s = __logf(1.0f + rough);
    float z1s = fminf(fmaxf(circ, 0.0f), 1.0f);
    float z2s = __logf(1.0f + ncv);
    float z3s = fminf(fmaxf(ent, 0.0f), 3.4657359f);
    E = g_par[8 ]*(g_par[0]*z0s + g_par[4])
      + g_par[9 ]*(g_par[1]*z1s + g_par[5])
      + g_par[10]*(g_par[2]*z2s + g_par[6])
      + g_par[11]*(g_par[3]*z3s + g_par[7]);
}

__device__ __forceinline__ float bnd_invden(int gx, int gy){
    int rows_in = ((gy+4 > HH-1 ? HH-1 : gy+4) - (gy-4 < 0 ? 0 : gy-4) + 1);
    int cols_in = ((gx+4 > WW-1 ? WW-1 : gx+4) - (gx-4 < 0 ? 0 : gx-4) + 1);
    return __fdividef(1.0f, (float)(rows_in*cols_in) + 1e-6f);
}

template<bool INTERIOR>
__device__ __forceinline__ void fused_body(
    float* __restrict__ out, int tx, int ty, int tid, int tx0, int ty0, int b,
    float* sg, float* p0, float* p1, float* vs0, float* vs1,
    unsigned* nucw, unsigned* cellw, unsigned* bndw,
    float& E00, float& E01, float& E10, float& E11)
{
    const float* g = g_gray + (size_t)b*HW;

    for (int idx = tid; idx < 42*42; idx += 256){
        int rr = idx/42, cc = idx%42;
        int gy = ty0 - 5 + rr, gx = tx0 - 5 + cc;
        float v;
        if (INTERIOR){
            v = g[gy*WW + gx];
        } else {
            v = 0.0f;
            if (gy >= 0 && gy < HH && gx >= 0 && gx < WW) v = g[gy*WW + gx];
        }
        sg[rr*43 + cc] = v;
    }
    {
        int kw0 = (tx0 >> 5) - 1;
        for (int idx = tid; idx < 120; idx += 256){
            int r = idx/3, c = idx%3;
            int gy = ty0 - 4 + r;
            int kw = kw0 + c;
            unsigned nv, cv, bv;
            if (INTERIOR){
                int off = b*WORDS_IMG + gy*WORDS_ROW + kw;
                nv = g_nucbits[off]; cv = g_cellbits[off]; bv = g_bndbits[off];
            } else {
                nv = 0; cv = 0; bv = 0;
                if (gy >= 0 && gy < HH && kw >= 0 && kw < WORDS_ROW){
                    int off = b*WORDS_IMG + gy*WORDS_ROW + kw;
                    nv = g_nucbits[off]; cv = g_cellbits[off]; bv = g_bndbits[off];
                }
            }
            nucw[idx] = nv; cellw[idx] = cv; bndw[idx] = bv;
        }
    }
    __syncthreads();

    // stage1: sobel -> unit vector on 40x40 halo
    for (int idx = tid; idx < 40*40; idx += 256){
        int r = idx/40, c = idx%40;
        float sn = 0.0f, cs = 1.0f;
        bool inb = true;
        if (!INTERIOR){
            int gy = ty0 - 4 + r, gx = tx0 - 4 + c;
            inb = (gy >= 0 && gy < HH && gx >= 0 && gx < WW);
        }
        if (inb){
            const float* p = sg + r*43 + c;
            float v00 = p[0],  v01 = p[1],  v02 = p[2];
            float v10 = p[43],              v12 = p[45];
            float v20 = p[86], v21 = p[87], v22 = p[88];
            float gxv = (v00 + 2.0f*v10 + v20) - (v02 + 2.0f*v12 + v22);
            float gyv = (v00 + 2.0f*v01 + v02) - (v20 + 2.0f*v21 + v22);
            float r2 = gxv*gxv + gyv*gyv;
            if (r2 > 0.0f){
                float inv = rsqrtf(r2);
                sn = gyv*inv; cs = gxv*inv;
            } else { sn = 0.0f; cs = 1.0f; }
        } else { sn = 0.0f; cs = 0.0f; }
        p0[idx] = sn; p1[idx] = cs;
    }
    __syncthreads();

    // stage2a: vertical 9-sums of sin/cos, row-pair incremental
    for (int idx = tid; idx < 16*40; idx += 256){
        int pr = idx/40, j = idx - pr*40;
        int y0 = 2*pr;
        float a0 = 0.0f, b0 = 0.0f;
        #pragma unroll
        for (int k = 0; k < 9; k++){
            a0 += p0[(y0+k)*40 + j];
            b0 += p1[(y0+k)*40 + j];
        }
        float a1 = a0 - p0[y0*40 + j] + p0[(y0+9)*40 + j];
        float b1 = b0 - p1[y0*40 + j] + p1[(y0+9)*40 + j];
        vs0[y0*40 + j] = a0; vs0[(y0+1)*40 + j] = a1;
        vs1[y0*40 + j] = b0; vs1[(y0+1)*40 + j] = b1;
    }
    __syncthreads();

    // stage2b: vertical 9-sums of gray/gray^2 into reused p0/p1
    for (int idx = tid; idx < 16*40; idx += 256){
        int pr = idx/40, j = idx - pr*40;
        int y0 = 2*pr;
        float c0 = 0.0f, d0 = 0.0f;
        #pragma unroll
        for (int k = 0; k < 9; k++){
            float gv = sg[(y0+1+k)*43 + (j+1)];
            c0 += gv;
            d0 += gv*gv;
        }
        float gold = sg[(y0+1)*43 + (j+1)];
        float gnew = sg[(y0+10)*43 + (j+1)];
        float c1 = c0 - gold + gnew;
        float d1 = d0 - gold*gold + gnew*gnew;
        p0[y0*40 + j] = c0; p0[(y0+1)*40 + j] = c1;
        p1[y0*40 + j] = d0; p1[(y0+1)*40 + j] = d1;
    }
    __syncthreads();

    // stage3: 2x2 quad per thread
    int xi0 = 2*tx;
    int yi0 = 2*ty, yi1 = yi0 + 1;
    int gx0 = tx0 + xi0;
    int gy0 = ty0 + yi0, gy1 = gy0 + 1;

    int anA = 0, anB = 0, csA = 0, csB = 0;
    #pragma unroll
    for (int k = 0; k < 10; k++){
        unsigned wn = winN(&nucw[(yi0+k)*3],  xi0 + 28, 10);
        unsigned wc = winN(&cellw[(yi0+k)*3], xi0 + 28, 10);
        int pn = __popc(wn)*0x10001 - (int)((wn >> 9) & 1u) - (int)((wn & 1u) << 16);
        int pc = __popc(wc)*0x10001 - (int)((wc >> 9) & 1u) - (int)((wc & 1u) << 16);
        if (k < 9){ anA += pn; csA += pc; }
        if (k > 0){ anB += pn; csB += pc; }
    }
    int bsA = 0, bsB = 0;
    #pragma unroll
    for (int k = 0; k < 6; k++){
        unsigned wb = winN(&bndw[(yi0+2+k)*3], xi0 + 30, 6);
        int pb = __popc(wb)*0x10001 - (int)((wb >> 5) & 1u) - (int)((wb & 1u) << 16);
        if (k < 5) bsA += pb;
        if (k > 0) bsB += pb;
    }

    unsigned wA = winN(&nucw[(yi0+3)*3], xi0 + 32, 2);
    unsigned wB = winN(&nucw[(yi0+4)*3], xi0 + 31, 4);
    unsigned wC = winN(&nucw[(yi0+5)*3], xi0 + 31, 4);
    unsigned wD = winN(&nucw[(yi0+6)*3], xi0 + 32, 2);
    unsigned bBv = winN(&bndw[(yi0+4)*3], xi0 + 32, 2);
    unsigned bCv = winN(&bndw[(yi0+5)*3], xi0 + 32, 2);

    unsigned a0b = wA & 1u,        a1b = (wA >> 1) & 1u;
    unsigned b0b = wB & 1u,        b1b = (wB >> 1) & 1u, b2b = (wB >> 2) & 1u, b3b = (wB >> 3) & 1u;
    unsigned c0b = wC & 1u,        c1b = (wC >> 1) & 1u, c2b = (wC >> 2) & 1u, c3b = (wC >> 3) & 1u;
    unsigned d0b = wD & 1u,        d1b = (wD >> 1) & 1u;

    float lap00 = fabsf((float)(a0b + c1b + b0b + b2b) - 4.0f*(float)b1b);
    float lap01 = fabsf((float)(a1b + c2b + b1b + b3b) - 4.0f*(float)b2b);
    float lap10 = fabsf((float)(b1b + d0b + c0b + c2b) - 4.0f*(float)c1b);
    float lap11 = fabsf((float)(b2b + d1b + c1b + c3b) - 4.0f*(float)c2b);

    const float INV81 = 1.0f/(81.0f + 1e-6f);

    float* zbase = out + (size_t)NPIX + (size_t)b*4*HW;
    float* nbase = out + 5*(size_t)NPIX + (size_t)b*HW;
    float* ebase = out + 6*(size_t)NPIX + (size_t)b*HW;

    // --- row y0 ---
    {
        float a0, a1, q0, q1, c0, c1, d0, d1;
        hsum2(vs0, yi0, xi0, a0, a1);
        hsum2(vs1, yi0, xi0, q0, q1);
        hsum2(p0,  yi0, xi0, c0, c1);
        hsum2(p1,  yi0, xi0, d0, d1);
        float inv0 = INTERIOR ? INV81 : bnd_invden(gx0,   gy0);
        float inv1 = INTERIOR ? INV81 : bnd_invden(gx0+1, gy0);
        float r0, ci0, n0, e0, r1, ci1, n1, e1;
        maps_pixel(inv0, a0, q0, c0, d0, anA & 0xFFFF, csA & 0xFFFF,
                   lap00, bBv & 1u, bsA & 0xFFFF, r0, ci0, n0, e0, E00);
        maps_pixel(inv1, a1, q1, c1, d1, anA >> 16, csA >> 16,
                   lap01, (bBv >> 1) & 1u, bsA >> 16, r1, ci1, n1, e1, E01);
        size_t pix = (size_t)gy0*WW + gx0;
        __stcs((float2*)(zbase + pix),        make_float2(r0, r1));
        __stcs((float2*)(zbase + HW + pix),   make_float2(ci0, ci1));
        __stcs((float2*)(zbase + 2*HW + pix), make_float2(n0, n1));
        __stcs((float2*)(zbase + 3*HW + pix), make_float2(e0, e1));
        __stcs((float2*)(nbase + pix),        make_float2((float)b1b, (float)b2b));
        *(float2*)(ebase + pix) = make_float2(E00, E01);   // re-read by k_A
    }
    // --- row y1 ---
    {
        float a0, a1, q0, q1, c0, c1, d0, d1;
        hsum2(vs0, yi1, xi0, a0, a1);
        hsum2(vs1, yi1, xi0, q0, q1);
        hsum2(p0,  yi1, xi0, c0, c1);
        hsum2(p1,  yi1, xi0, d0, d1);
        float inv0 = INTERIOR ? INV81 : bnd_invden(gx0,   gy1);
        float inv1 = INTERIOR ? INV81 : bnd_invden(gx0+1, gy1);
        float r0, ci0, n0, e0, r1, ci1, n1, e1;
        maps_pixel(inv0, a0, q0, c0, d0, anB & 0xFFFF, csB & 0xFFFF,
                   lap10, bCv & 1u, bsB & 0xFFFF, r0, ci0, n0, e0, E10);
        maps_pixel(inv1, a1, q1, c1, d1, anB >> 16, csB >> 16,
                   lap11, (bCv >> 1) & 1u, bsB >> 16, r1, ci1, n1, e1, E11);
        size_t pix = (size_t)gy1*WW + gx0;
        __stcs((float2*)(zbase + pix),        make_float2(r0, r1));
        __stcs((float2*)(zbase + HW + pix),   make_float2(ci0, ci1));
        __stcs((float2*)(zbase + 2*HW + pix), make_float2(n0, n1));
        __stcs((float2*)(zbase + 3*HW + pix), make_float2(e0, e1));
        __stcs((float2*)(nbase + pix),        make_float2((float)c1b, (float)c2b));
        *(float2*)(ebase + pix) = make_float2(E10, E11);
    }
}

__global__ void __launch_bounds__(256, 5) k_fused(float* __restrict__ out){
    __shared__ float sg[42*43];
    __shared__ float p0[40*40];
    __shared__ float p1[40*40];
    __shared__ float vs0[32*40], vs1[32*40];
    __shared__ unsigned nucw[40*3], cellw[40*3], bndw[40*3];
    __shared__ float wred[8];

    int tx = threadIdx.x, ty = threadIdx.y;   // 16 x 16
    int tid = ty*16 + tx;
    int tx0 = blockIdx.x*32, ty0 = blockIdx.y*32;
    int b = blockIdx.z;

    bool interior = (blockIdx.x > 0) && (blockIdx.x < 15) && (blockIdx.y > 0) && (blockIdx.y < 15);

    float E00, E01, E10, E11;
    if (interior)
        fused_body<true >(out, tx, ty, tid, tx0, ty0, b, sg, p0, p1, vs0, vs1, nucw, cellw, bndw, E00, E01, E10, E11);
    else
        fused_body<false>(out, tx, ty, tid, tx0, ty0, b, sg, p0, p1, vs0, vs1, nucw, cellw, bndw, E00, E01, E10, E11);

    // softmax partials (8 warps)
    int lane = tid & 31, wid = tid >> 5;
    float invtau = __fdividef(1.0f, g_par[12]);
    float z00 = -E00*invtau, z01 = -E01*invtau, z10 = -E10*invtau, z11 = -E11*invtau;
    float m = fmaxf(fmaxf(z00, z01), fmaxf(z10, z11));
    #pragma unroll
    for (int o = 16; o > 0; o >>= 1) m = fmaxf(m, __shfl_xor_sync(0xFFFFFFFFu, m, o));
    if (lane == 0) wred[wid] = m;
    __syncthreads();
    if (wid == 0){
        float mm = (lane < 8) ? wred[lane] : -1e30f;
        #pragma unroll
        for (int o = 4; o > 0; o >>= 1) mm = fmaxf(mm, __shfl_xor_sync(0xFFFFFFFFu, mm, o));
        if (lane == 0) wred[0] = mm;
    }
    __syncthreads();
    float M = wred[0];
    float e = __expf(z00 - M) + __expf(z01 - M) + __expf(z10 - M) + __expf(z11 - M);
    #pragma unroll
    for (int o = 16; o > 0; o >>= 1) e += __shfl_xor_sync(0xFFFFFFFFu, e, o);
    __syncthreads();
    if (lane == 0) wred[wid] = e;
    __syncthreads();
    if (wid == 0){
        float ss = (lane < 8) ? wred[lane] : 0.0f;
        #pragma unroll
        for (int o = 4; o > 0; o >>= 1) ss += __shfl_xor_sync(0xFFFFFFFFu, ss, o);
        if (lane == 0){
            int tile = blockIdx.y*16 + blockIdx.x;
            g_part[(b*256 + tile)*2    ] = M;
            g_part[(b*256 + tile)*2 + 1] = ss;
        }
    }
}

// ---------------- final A (512 threads; inlines the partial combine) ----------------
__global__ void __launch_bounds__(512) k_A(float* __restrict__ out){
    __shared__ float wred[16];
    __shared__ float fin[2];
    int b = blockIdx.y;
    int t = threadIdx.x;
    int lane = t & 31, wid = t >> 5;

    float m = -1e30f, s = 0.0f;
    if (t < 256){
        m = g_part[(b*256 + t)*2];
        s = g_part[(b*256 + t)*2 + 1];
    }
    float mm = m;
    #pragma unroll
    for (int o = 16; o > 0; o >>= 1) mm = fmaxf(mm, __shfl_xor_sync(0xFFFFFFFFu, mm, o));
    if (lane == 0 && wid < 8) wred[wid] = mm;
    __syncthreads();
    if (wid == 0){
        float v = (lane < 8) ? wred[lane] : -1e30f;
        #pragma unroll
        for (int o = 4; o > 0; o >>= 1) v = fmaxf(v, __shfl_xor_sync(0xFFFFFFFFu, v, o));
        if (lane == 0) fin[0] = v;
    }
    __syncthreads();
    float M = fin[0];
    float e = (t < 256) ? s*__expf(m - M) : 0.0f;
    #pragma unroll
    for (int o = 16; o > 0; o >>= 1) e += __shfl_xor_sync(0xFFFFFFFFu, e, o);
    __syncthreads();
    if (lane == 0 && wid < 8) wred[wid] = e;
    __syncthreads();
    if (wid == 0){
        float v = (lane < 8) ? wred[lane] : 0.0f;
        #pragma unroll
        for (int o = 4; o > 0; o >>= 1) v += __shfl_xor_sync(0xFFFFFFFFu, v, o);
        if (lane == 0) fin[1] = v;
    }
    __syncthreads();
    float invS = __fdividef(1.0f, fin[1]);
    float invtau = __fdividef(1.0f, g_par[12]);

    int p4 = blockIdx.x*512 + t;
    float4 E4 = ((const float4*)(out + 6*(size_t)NPIX + (size_t)b*HW))[p4];
    float4 A4;
    A4.x = __expf(-E4.x*invtau - M)*invS;
    A4.y = __expf(-E4.y*invtau - M)*invS;
    A4.z = __expf(-E4.z*invtau - M)*invS;
    A4.w = __expf(-E4.w*invtau - M)*invS;
    __stcs((float4*)(out + (size_t)b*HW) + p4, A4);
}

// ---------------- launch ----------------
extern "C" void kernel_launch(void* const* d_in, const int* in_sizes, int n_in,
                              void* d_out, int out_size){
    const float* img    = (const float*)d_in[0];
    const float* cal_a  = (const float*)d_in[1];
    const float* cal_b  = (const float*)d_in[2];
    const float* alpha  = (const float*)d_in[3];
    const float* tau_p  = (const float*)d_in[4];
    float* out = (float*)d_out;
    (void)in_sizes; (void)n_in; (void)out_size;

    k_gray_hist<<<dim3(HW/(256*4), BB, 1), 256>>>(img);
    k_otsu_params<<<BB, 32>>>(cal_a, cal_b, alpha, tau_p);
    k_morph<<<dim3(HH/TR, BB, 1), MT>>>();
    k_fused<<<dim3(16, 16, BB), dim3(16, 16, 1)>>>(out);
    k_A<<<dim3(HW/(512*4), BB, 1), 512>>>(out);
}

// round 17
// speedup vs baseline: 1.0745x; 1.0185x over previous
#include <cuda_runtime.h>
#include <math.h>

#define BB 16
#define HH 512
#define WW 512
#define HW (HH*WW)
#define NPIX (BB*HW)
#define WORDS_ROW 16           // 512/32
#define WORDS_IMG (HH*WORDS_ROW)

// morph tiling (TR=16: best measured config)
#define TR 16
#define HALO 9
#define SR (TR + 2*HALO)       // 34 rows
#define SW (SR*WORDS_ROW)      // 544 words
#define MT 256

// ---------------- scratch (device globals: alloc-free rule) ----------------
static __device__ float    g_gray[NPIX];
static __device__ int      g_hist[BB*32];
static __device__ float    g_thr[BB];
static __device__ unsigned g_nucbits[BB*WORDS_IMG];
static __device__ unsigned g_cellbits[BB*WORDS_IMG];
static __device__ unsigned g_bndbits[BB*WORDS_IMG];
static __device__ float    g_par[13];          // sp(cal_a)[4], cal_b[4], alpha[4], tau
static __device__ float    g_part[BB*256*2];   // per-tile (max, sumexp)

__device__ __forceinline__ float softplusf(float v){
    return fmaxf(v, 0.0f) + log1pf(expf(-fabsf(v)));
}

// ---------------- gray + histogram (float4, per-warp hist) ----------------
__global__ void k_gray_hist(const float* __restrict__ img){
    __shared__ int sh[8][32];
    int t = threadIdx.x;
    int w = t >> 5;
    ((int*)sh)[t] = 0;
    __syncthreads();
    int b = blockIdx.y;
    int p4 = blockIdx.x*blockDim.x + t;
    const float4* imr = (const float4*)(img + (size_t)b*3*HW);
    const float4* img_ = imr + (HW/4);
    const float4* imb = imr + 2*(HW/4);
    float4 r4 = __ldcs(imr + p4);
    float4 g4 = __ldcs(img_ + p4);
    float4 b4 = __ldcs(imb + p4);
    float gr[4];
    gr[0] = 0.5f*(0.299f*r4.x + 0.587f*g4.x + 0.114f*b4.x + 1.0f);
    gr[1] = 0.5f*(0.299f*r4.y + 0.587f*g4.y + 0.114f*b4.y + 1.0f);
    gr[2] = 0.5f*(0.299f*r4.z + 0.587f*g4.z + 0.114f*b4.z + 1.0f);
    gr[3] = 0.5f*(0.299f*r4.w + 0.587f*g4.w + 0.114f*b4.w + 1.0f);
    float4 o;
    #pragma unroll
    for (int j = 0; j < 4; j++){
        gr[j] = fminf(fmaxf(gr[j], 0.0f), 1.0f);
        int idx = (int)(gr[j]*32.0f);
        idx = idx < 0 ? 0 : (idx > 31 ? 31 : idx);
        atomicAdd(&sh[w][idx], 1);
    }
    o.x = gr[0]; o.y = gr[1]; o.z = gr[2]; o.w = gr[3];
    ((float4*)(g_gray + (size_t)b*HW))[p4] = o;
    __syncthreads();
    if (t < 32){
        int acc = 0;
        #pragma unroll
        for (int ww = 0; ww < 8; ww++) acc += sh[ww][t];
        atomicAdd(&g_hist[b*32 + t], acc);
    }
}

// ---------------- Otsu + scalar params (consumes + resets hist) ----------------
__global__ void k_otsu_params(const float* __restrict__ cal_a, const float* __restrict__ cal_b,
                              const float* __restrict__ alpha_logits, const float* __restrict__ tau_p){
    int b = blockIdx.x;
    if (threadIdx.x != 0) return;
    float omega[32], mu[32];
    float denom = (float)HW + 1e-6f;
    float o = 0.0f, m = 0.0f;
    for (int k = 0; k < 32; k++){
        float pk = (float)g_hist[b*32 + k] / denom;
        float xk = (float)k / 31.0f;
        o += pk; m += pk*xk;
        omega[k] = o; mu[k] = m;
    }
    for (int k = 0; k < 32; k++) g_hist[b*32 + k] = 0;
    float mu_t = mu[31];
    float best = -1e30f; int kb = 0;
    for (int k = 0; k < 32; k++){
        float num = mu_t*omega[k] - mu[k];
        float s   = num*num / (omega[k]*(1.0f - omega[k]) + 1e-8f);
        if (s > best){ best = s; kb = k; }
    }
    g_thr[b] = (float)kb / 32.0f;
    if (b == 0){
        float al[4]; float mx = -1e30f;
        for (int c = 0; c < 4; c++){ al[c] = alpha_logits[c]; mx = fmaxf(mx, al[c]); }
        float s = 0.0f;
        for (int c = 0; c < 4; c++){ al[c] = expf(al[c] - mx); s += al[c]; }
        for (int c = 0; c < 4; c++){
            g_par[c]     = softplusf(cal_a[c]);
            g_par[4 + c] = cal_b[c];
            g_par[8 + c] = al[c]/s;
        }
        g_par[12] = 0.2f + softplusf(tau_p[0]);
    }
}

// ---------------- bit-packed morphology (double-buffered, TR=16) ----------------
__device__ __forceinline__ unsigned h_ero(const unsigned* S, int r, int k){
    unsigned w = S[r*WORDS_ROW + k];
    unsigned p = (k > 0)             ? S[r*WORDS_ROW + k - 1] : 0u;
    unsigned n = (k < WORDS_ROW - 1) ? S[r*WORDS_ROW + k + 1] : 0u;
    unsigned L = (w << 1) | ((k > 0)             ? (p >> 31) : 1u);
    unsigned R = (w >> 1) | ((k < WORDS_ROW - 1) ? (n << 31) : 0x80000000u);
    return L & w & R;
}
__device__ __forceinline__ unsigned h_dil(const unsigned* S, int r, int k){
    unsigned w = S[r*WORDS_ROW + k];
    unsigned p = (k > 0)             ? S[r*WORDS_ROW + k - 1] : 0u;
    unsigned n = (k < WORDS_ROW - 1) ? S[r*WORDS_ROW + k + 1] : 0u;
    unsigned L = (w << 1) | (p >> 31);
    unsigned R = (w >> 1) | (n << 31);
    return L | w | R;
}
__device__ __forceinline__ unsigned erode3T(const unsigned* S, int r, int k, int gy){
    unsigned v = h_ero(S, r, k);
    if (gy > 0     && r > 0)      v &= h_ero(S, r-1, k);
    if (gy < HH-1  && r < SR-1)   v &= h_ero(S, r+1, k);
    return v;
}
__device__ __forceinline__ unsigned dilate3T(const unsigned* S, int r, int k, int gy){
    unsigned v = h_dil(S, r, k);
    if (gy > 0     && r > 0)      v |= h_dil(S, r-1, k);
    if (gy < HH-1  && r < SR-1)   v |= h_dil(S, r+1, k);
    return v;
}

#define MORPH_STEP2(FN, src, dst)                                   \
    {                                                               \
        _Pragma("unroll")                                           \
        for (int s = 0; s < 3; s++){                                \
            int idx = tid + s*MT;                                   \
            if (idx < SW){                                          \
                int r = idx >> 4, k = idx & 15;                     \
                (dst)[idx] = FN((src), r, k, ty0 - HALO + r);       \
            }                                                       \
        }                                                           \
        __syncthreads();                                            \
    }

__global__ void __launch_bounds__(MT) k_morph(){
    __shared__ unsigned S0[SW];
    __shared__ unsigned S1[SW];
    int b   = blockIdx.y;
    int ty0 = blockIdx.x*TR;
    int tid = threadIdx.x;
    float thr = g_thr[b];
    const float* g = g_gray + (size_t)b*HW;

    #pragma unroll
    for (int s = 0; s < 3; s++){
        int idx = tid + s*MT;
        if (idx < SW){
            int r = idx >> 4, k = idx & 15;
            int gy = ty0 - HALO + r;
            unsigned w = 0;
            if (gy >= 0 && gy < HH){
                const float4* row = (const float4*)(g + gy*WW + k*32);
                #pragma unroll
                for (int j = 0; j < 8; j++){
                    float4 v4 = row[j];
                    w |= (v4.x <= thr ? 1u : 0u) << (4*j);
                    w |= (v4.y <= thr ? 1u : 0u) << (4*j+1);
                    w |= (v4.z <= thr ? 1u : 0u) << (4*j+2);
                    w |= (v4.w <= thr ? 1u : 0u) << (4*j+3);
                }
            }
            S0[idx] = w;
        }
    }
    __syncthreads();

    MORPH_STEP2(erode3T,  S0, S1)
    MORPH_STEP2(dilate3T, S1, S0)
    MORPH_STEP2(dilate3T, S0, S1)
    MORPH_STEP2(erode3T,  S1, S0)   // S0 = nuc

    {
        int idx = tid;
        int r = (idx >> 4) + HALO, k = idx & 15;
        int gy = ty0 - HALO + r;
        unsigned nu = S0[r*WORDS_ROW + k];
        unsigned er = erode3T(S0, r, k, gy);
        g_nucbits[b*WORDS_IMG + gy*WORDS_ROW + k] = nu;
        g_bndbits[b*WORDS_IMG + gy*WORDS_ROW + k] = nu & ~er;
    }
    #pragma unroll
    for (int s = 0; s < 3; s++){
        int idx = tid + s*MT;
        if (idx < SW){
            int r = idx >> 4, k = idx & 15;
            unsigned w = S0[r*WORDS_ROW + k];
            unsigned p = (k > 0)             ? S0[r*WORDS_ROW + k - 1] : 0u;
            unsigned n = (k < WORDS_ROW - 1) ? S0[r*WORDS_ROW + k + 1] : 0u;
            unsigned long long lo = ((unsigned long long)w << 32) | p;
            unsigned long long hi = ((unsigned long long)n << 32) | w;
            unsigned v = w;
            #pragma unroll
            for (int sh = 1; sh <= 5; sh++){
                v |= (unsigned)(lo >> (32 - sh));
                v |= (unsigned)(hi >> sh);
            }
            S1[idx] = v;
        }
    }
    __syncthreads();
    {
        int idx = tid;
        int r = (idx >> 4) + HALO, k = idx & 15;
        int gy = ty0 - HALO + r;
        int d0 = (gy - 5 < 0)    ? -gy          : -5;
        int d1 = (gy + 5 > HH-1) ? (HH-1 - gy)  :  5;
        unsigned v = 0;
        for (int d = d0; d <= d1; d++) v |= S1[(r + d)*WORDS_ROW + k];
        g_cellbits[b*WORDS_IMG + gy*WORDS_ROW + k] = v;
    }
}

// ---------------- fused maps kernel (2x2 quad, interior/boundary paths) ----------------
__device__ __forceinline__ unsigned winN(const unsigned* w3, int rel, int width){
    unsigned long long c = ((unsigned long long)w3[1] << 32) | (unsigned long long)w3[0];
    unsigned long long v = c >> rel;
    if (rel + width > 64) v |= ((unsigned long long)w3[2]) << (64 - rel);
    return (unsigned)v & ((1u << width) - 1u);
}

__device__ __forceinline__ void hsum2(const float* P, int yi, int xi0, float& s0, float& s1){
    const float* row = P + yi*40 + xi0;
    float t0 = row[0];
    float s = t0 + row[1] + row[2] + row[3] + row[4]
                 + row[5] + row[6] + row[7] + row[8];
    s0 = s;
    s1 = s - t0 + row[9];
}

__device__ __forceinline__ void maps_pixel(
    float invden,
    float s_sn, float s_cs, float s_g, float s_g2,
    int an, int csum, float lap, unsigned bc, int bs,
    float& rough, float& circ, float& ncv, float& ent, float& E)
{
    float ms = s_sn*invden, mc = s_cs*invden;
    float t = ms*ms + mc*mc + 1e-6f;
    circ = 1.0f - t*rsqrtf(t);
    float g1 = s_g*invden, g2v = s_g2*invden;
    ent = __logf(1.0f + fmaxf(g2v - g1*g1, 0.0f));
    float A_c = fmaxf((float)(csum - an), 1.0f);
    ncv = __fdividef((float)an, A_c);
    rough = lap*(float)bc*__fdividef(1.0f, (float)bs + 1e-6f);

    float z0s = __logf(1.0f + rough);
    float z1s = fminf(fmaxf(circ, 0.0f), 1.0f);
    float z2s = __logf(1.0f + ncv);
    float z3s = fminf(fmaxf(ent, 0.0f), 3.4657359f);
    E = g_par[8 ]*(g_par[0]*z0s + g_par[4])
      + g_par[9 ]*(g_par[1]*z1s + g_par[5])
      + g_par[10]*(g_par[2]*z2s + g_par[6])
      + g_par[11]*(g_par[3]*z3s + g_par[7]);
}

__device__ __forceinline__ float bnd_invden(int gx, int gy){
    int rows_in = ((gy+4 > HH-1 ? HH-1 : gy+4) - (gy-4 < 0 ? 0 : gy-4) + 1);
    int cols_in = ((gx+4 > WW-1 ? WW-1 : gx+4) - (gx-4 < 0 ? 0 : gx-4) + 1);
    return __fdividef(1.0f, (float)(rows_in*cols_in) + 1e-6f);
}

template<bool INTERIOR>
__device__ __forceinline__ void fused_body(
    float* __restrict__ out, int tx, int ty, int tid, int tx0, int ty0, int b,
    float* sg, float* p0, float* p1, float* vs0, float* vs1,
    unsigned* nucw, unsigned* cellw, unsigned* bndw,
    float& E00, float& E01, float& E10, float& E11)
{
    const float* g = g_gray + (size_t)b*HW;

    for (int idx = tid; idx < 42*42; idx += 256){
        int rr = idx/42, cc = idx%42;
        int gy = ty0 - 5 + rr, gx = tx0 - 5 + cc;
        float v;
        if (INTERIOR){
            v = g[gy*WW + gx];
        } else {
            v = 0.0f;
            if (gy >= 0 && gy < HH && gx >= 0 && gx < WW) v = g[gy*WW + gx];
        }
        sg[rr*43 + cc] = v;
    }
    {
        int kw0 = (tx0 >> 5) - 1;
        for (int idx = tid; idx < 120; idx += 256){
            int r = idx/3, c = idx%3;
            int gy = ty0 - 4 + r;
            int kw = kw0 + c;
            unsigned nv, cv, bv;
            if (INTERIOR){
                int off = b*WORDS_IMG + gy*WORDS_ROW + kw;
                nv = g_nucbits[off]; cv = g_cellbits[off]; bv = g_bndbits[off];
            } else {
                nv = 0; cv = 0; bv = 0;
                if (gy >= 0 && gy < HH && kw >= 0 && kw < WORDS_ROW){
                    int off = b*WORDS_IMG + gy*WORDS_ROW + kw;
                    nv = g_nucbits[off]; cv = g_cellbits[off]; bv = g_bndbits[off];
                }
            }
            nucw[idx] = nv; cellw[idx] = cv; bndw[idx] = bv;
        }
    }
    __syncthreads();

    // stage1: sobel -> unit vector on 40x40 halo
    for (int idx = tid; idx < 40*40; idx += 256){
        int r = idx/40, c = idx%40;
        float sn = 0.0f, cs = 1.0f;
        bool inb = true;
        if (!INTERIOR){
            int gy = ty0 - 4 + r, gx = tx0 - 4 + c;
            inb = (gy >= 0 && gy < HH && gx >= 0 && gx < WW);
        }
        if (inb){
            const float* p = sg + r*43 + c;
            float v00 = p[0],  v01 = p[1],  v02 = p[2];
            float v10 = p[43],              v12 = p[45];
            float v20 = p[86], v21 = p[87], v22 = p[88];
            float gxv = (v00 + 2.0f*v10 + v20) - (v02 + 2.0f*v12 + v22);
            float gyv = (v00 + 2.0f*v01 + v02) - (v20 + 2.0f*v21 + v22);
            float r2 = gxv*gxv + gyv*gyv;
            if (r2 > 0.0f){
                float inv = rsqrtf(r2);
                sn = gyv*inv; cs = gxv*inv;
            } else { sn = 0.0f; cs = 1.0f; }
        } else { sn = 0.0f; cs = 0.0f; }
        p0[idx] = sn; p1[idx] = cs;
    }
    __syncthreads();

    // stage2a: vertical 9-sums of sin/cos, row-pair incremental
    for (int idx = tid; idx < 16*40; idx += 256){
        int pr = idx/40, j = idx - pr*40;
        int y0 = 2*pr;
        float a0 = 0.0f, b0 = 0.0f;
        #pragma unroll
        for (int k = 0; k < 9; k++){
            a0 += p0[(y0+k)*40 + j];
            b0 += p1[(y0+k)*40 + j];
        }
        float a1 = a0 - p0[y0*40 + j] + p0[(y0+9)*40 + j];
        float b1 = b0 - p1[y0*40 + j] + p1[(y0+9)*40 + j];
        vs0[y0*40 + j] = a0; vs0[(y0+1)*40 + j] = a1;
        vs1[y0*40 + j] = b0; vs1[(y0+1)*40 + j] = b1;
    }
    __syncthreads();

    // stage2b: vertical 9-sums of gray/gray^2 into reused p0/p1
    for (int idx = tid; idx < 16*40; idx += 256){
        int pr = idx/40, j = idx - pr*40;
        int y0 = 2*pr;
        float c0 = 0.0f, d0 = 0.0f;
        #pragma unroll
        for (int k = 0; k < 9; k++){
            float gv = sg[(y0+1+k)*43 + (j+1)];
            c0 += gv;
            d0 += gv*gv;
        }
        float gold = sg[(y0+1)*43 + (j+1)];
        float gnew = sg[(y0+10)*43 + (j+1)];
        float c1 = c0 - gold + gnew;
        float d1 = d0 - gold*gold + gnew*gnew;
        p0[y0*40 + j] = c0; p0[(y0+1)*40 + j] = c1;
        p1[y0*40 + j] = d0; p1[(y0+1)*40 + j] = d1;
    }
    __syncthreads();

    // stage3: 2x2 quad per thread
    int xi0 = 2*tx;
    int yi0 = 2*ty, yi1 = yi0 + 1;
    int gx0 = tx0 + xi0;
    int gy0 = ty0 + yi0, gy1 = gy0 + 1;

    int anA = 0, anB = 0, csA = 0, csB = 0;
    #pragma unroll
    for (int k = 0; k < 10; k++){
        unsigned wn = winN(&nucw[(yi0+k)*3],  xi0 + 28, 10);
        unsigned wc = winN(&cellw[(yi0+k)*3], xi0 + 28, 10);
        int pn = __popc(wn)*0x10001 - (int)((wn >> 9) & 1u) - (int)((wn & 1u) << 16);
        int pc = __popc(wc)*0x10001 - (int)((wc >> 9) & 1u) - (int)((wc & 1u) << 16);
        if (k < 9){ anA += pn; csA += pc; }
        if (k > 0){ anB += pn; csB += pc; }
    }
    int bsA = 0, bsB = 0;
    #pragma unroll
    for (int k = 0; k < 6; k++){
        unsigned wb = winN(&bndw[(yi0+2+k)*3], xi0 + 30, 6);
        int pb = __popc(wb)*0x10001 - (int)((wb >> 5) & 1u) - (int)((wb & 1u) << 16);
        if (k < 5) bsA += pb;
        if (k > 0) bsB += pb;
    }

    unsigned wA = winN(&nucw[(yi0+3)*3], xi0 + 32, 2);
    unsigned wB = winN(&nucw[(yi0+4)*3], xi0 + 31, 4);
    unsigned wC = winN(&nucw[(yi0+5)*3], xi0 + 31, 4);
    unsigned wD = winN(&nucw[(yi0+6)*3], xi0 + 32, 2);
    unsigned bBv = winN(&bndw[(yi0+4)*3], xi0 + 32, 2);
    unsigned bCv = winN(&bndw[(yi0+5)*3], xi0 + 32, 2);

    unsigned a0b = wA & 1u,        a1b = (wA >> 1) & 1u;
    unsigned b0b = wB & 1u,        b1b = (wB >> 1) & 1u, b2b = (wB >> 2) & 1u, b3b = (wB >> 3) & 1u;
    unsigned c0b = wC & 1u,        c1b = (wC >> 1) & 1u, c2b = (wC >> 2) & 1u, c3b = (wC >> 3) & 1u;
    unsigned d0b = wD & 1u,        d1b = (wD >> 1) & 1u;

    float lap00 = fabsf((float)(a0b + c1b + b0b + b2b) - 4.0f*(float)b1b);
    float lap01 = fabsf((float)(a1b + c2b + b1b + b3b) - 4.0f*(float)b2b);
    float lap10 = fabsf((float)(b1b + d0b + c0b + c2b) - 4.0f*(float)c1b);
    float lap11 = fabsf((float)(b2b + d1b + c1b + c3b) - 4.0f*(float)c2b);

    const float INV81 = 1.0f/(81.0f + 1e-6f);

    float* zbase = out + (size_t)NPIX + (size_t)b*4*HW;
    float* nbase = out + 5*(size_t)NPIX + (size_t)b*HW;
    float* ebase = out + 6*(size_t)NPIX + (size_t)b*HW;

    // --- row y0 ---
    {
        float a0, a1, q0, q1, c0, c1, d0, d1;
        hsum2(vs0, yi0, xi0, a0, a1);
        hsum2(vs1, yi0, xi0, q0, q1);
        hsum2(p0,  yi0, xi0, c0, c1);
        hsum2(p1,  yi0, xi0, d0, d1);
        float inv0 = INTERIOR ? INV81 : bnd_invden(gx0,   gy0);
        float inv1 = INTERIOR ? INV81 : bnd_invden(gx0+1, gy0);
        float r0, ci0, n0, e0, r1, ci1, n1, e1;
        maps_pixel(inv0, a0, q0, c0, d0, anA & 0xFFFF, csA & 0xFFFF,
                   lap00, bBv & 1u, bsA & 0xFFFF, r0, ci0, n0, e0, E00);
        maps_pixel(inv1, a1, q1, c1, d1, anA >> 16, csA >> 16,
                   lap01, (bBv >> 1) & 1u, bsA >> 16, r1, ci1, n1, e1, E01);
        size_t pix = (size_t)gy0*WW + gx0;
        __stcs((float2*)(zbase + pix),        make_float2(r0, r1));
        __stcs((float2*)(zbase + HW + pix),   make_float2(ci0, ci1));
        __stcs((float2*)(zbase + 2*HW + pix), make_float2(n0, n1));
        __stcs((float2*)(zbase + 3*HW + pix), make_float2(e0, e1));
        __stcs((float2*)(nbase + pix),        make_float2((float)b1b, (float)b2b));
        *(float2*)(ebase + pix) = make_float2(E00, E01);   // re-read by k_A
    }
    // --- row y1 ---
    {
        float a0, a1, q0, q1, c0, c1, d0, d1;
        hsum2(vs0, yi1, xi0, a0, a1);
        hsum2(vs1, yi1, xi0, q0, q1);
        hsum2(p0,  yi1, xi0, c0, c1);
        hsum2(p1,  yi1, xi0, d0, d1);
        float inv0 = INTERIOR ? INV81 : bnd_invden(gx0,   gy1);
        float inv1 = INTERIOR ? INV81 : bnd_invden(gx0+1, gy1);
        float r0, ci0, n0, e0, r1, ci1, n1, e1;
        maps_pixel(inv0, a0, q0, c0, d0, anB & 0xFFFF, csB & 0xFFFF,
                   lap10, bCv & 1u, bsB & 0xFFFF, r0, ci0, n0, e0, E10);
        maps_pixel(inv1, a1, q1, c1, d1, anB >> 16, csB >> 16,
                   lap11, (bCv >> 1) & 1u, bsB >> 16, r1, ci1, n1, e1, E11);
        size_t pix = (size_t)gy1*WW + gx0;
        __stcs((float2*)(zbase + pix),        make_float2(r0, r1));
        __stcs((float2*)(zbase + HW + pix),   make_float2(ci0, ci1));
        __stcs((float2*)(zbase + 2*HW + pix), make_float2(n0, n1));
        __stcs((float2*)(zbase + 3*HW + pix), make_float2(e0, e1));
        __stcs((float2*)(nbase + pix),        make_float2((float)c1b, (float)c2b));
        *(float2*)(ebase + pix) = make_float2(E10, E11);
    }
}

__global__ void __launch_bounds__(256, 6) k_fused(float* __restrict__ out){
    __shared__ float sg[42*43];
    __shared__ float p0[40*40];
    __shared__ float p1[40*40];
    __shared__ float vs0[32*40], vs1[32*40];
    __shared__ unsigned nucw[40*3], cellw[40*3], bndw[40*3];
    __shared__ float wred[8];

    int tx = threadIdx.x, ty = threadIdx.y;   // 16 x 16
    int tid = ty*16 + tx;
    int tx0 = blockIdx.x*32, ty0 = blockIdx.y*32;
    int b = blockIdx.z;

    bool interior = (blockIdx.x > 0) && (blockIdx.x < 15) && (blockIdx.y > 0) && (blockIdx.y < 15);

    float E00, E01, E10, E11;
    if (interior)
        fused_body<true >(out, tx, ty, tid, tx0, ty0, b, sg, p0, p1, vs0, vs1, nucw, cellw, bndw, E00, E01, E10, E11);
    else
        fused_body<false>(out, tx, ty, tid, tx0, ty0, b, sg, p0, p1, vs0, vs1, nucw, cellw, bndw, E00, E01, E10, E11);

    // softmax partials (8 warps)
    int lane = tid & 31, wid = tid >> 5;
    float invtau = __fdividef(1.0f, g_par[12]);
    float z00 = -E00*invtau, z01 = -E01*invtau, z10 = -E10*invtau, z11 = -E11*invtau;
    float m = fmaxf(fmaxf(z00, z01), fmaxf(z10, z11));
    #pragma unroll
    for (int o = 16; o > 0; o >>= 1) m = fmaxf(m, __shfl_xor_sync(0xFFFFFFFFu, m, o));
    if (lane == 0) wred[wid] = m;
    __syncthreads();
    if (wid == 0){
        float mm = (lane < 8) ? wred[lane] : -1e30f;
        #pragma unroll
        for (int o = 4; o > 0; o >>= 1) mm = fmaxf(mm, __shfl_xor_sync(0xFFFFFFFFu, mm, o));
        if (lane == 0) wred[0] = mm;
    }
    __syncthreads();
    float M = wred[0];
    float e = __expf(z00 - M) + __expf(z01 - M) + __expf(z10 - M) + __expf(z11 - M);
    #pragma unroll
    for (int o = 16; o > 0; o >>= 1) e += __shfl_xor_sync(0xFFFFFFFFu, e, o);
    __syncthreads();
    if (lane == 0) wred[wid] = e;
    __syncthreads();
    if (wid == 0){
        float ss = (lane < 8) ? wred[lane] : 0.0f;
        #pragma unroll
        for (int o = 4; o > 0; o >>= 1) ss += __shfl_xor_sync(0xFFFFFFFFu, ss, o);
        if (lane == 0){
            int tile = blockIdx.y*16 + blockIdx.x;
            g_part[(b*256 + tile)*2    ] = M;
            g_part[(b*256 + tile)*2 + 1] = ss;
        }
    }
}

// ---------------- final A (512 threads; inlines the partial combine) ----------------
__global__ void __launch_bounds__(512) k_A(float* __restrict__ out){
    __shared__ float wred[16];
    __shared__ float fin[2];
    int b = blockIdx.y;
    int t = threadIdx.x;
    int lane = t & 31, wid = t >> 5;

    float m = -1e30f, s = 0.0f;
    if (t < 256){
        m = g_part[(b*256 + t)*2];
        s = g_part[(b*256 + t)*2 + 1];
    }
    float mm = m;
    #pragma unroll
    for (int o = 16; o > 0; o >>= 1) mm = fmaxf(mm, __shfl_xor_sync(0xFFFFFFFFu, mm, o));
    if (lane == 0 && wid < 8) wred[wid] = mm;
    __syncthreads();
    if (wid == 0){
        float v = (lane < 8) ? wred[lane] : -1e30f;
        #pragma unroll
        for (int o = 4; o > 0; o >>= 1) v = fmaxf(v, __shfl_xor_sync(0xFFFFFFFFu, v, o));
        if (lane == 0) fin[0] = v;
    }
    __syncthreads();
    float M = fin[0];
    float e = (t < 256) ? s*__expf(m - M) : 0.0f;
    #pragma unroll
    for (int o = 16; o > 0; o >>= 1) e += __shfl_xor_sync(0xFFFFFFFFu, e, o);
    __syncthreads();
    if (lane == 0 && wid < 8) wred[wid] = e;
    __syncthreads();
    if (wid == 0){
        float v = (lane < 8) ? wred[lane] : 0.0f;
        #pragma unroll
        for (int o = 4; o > 0; o >>= 1) v += __shfl_xor_sync(0xFFFFFFFFu, v, o);
        if (lane == 0) fin[1] = v;
    }
    __syncthreads();
    float invS = __fdividef(1.0f, fin[1]);
    float invtau = __fdividef(1.0f, g_par[12]);

    int p4 = blockIdx.x*512 + t;
    float4 E4 = ((const float4*)(out + 6*(size_t)NPIX + (size_t)b*HW))[p4];
    float4 A4;
    A4.x = __expf(-E4.x*invtau - M)*invS;
    A4.y = __expf(-E4.y*invtau - M)*invS;
    A4.z = __expf(-E4.z*invtau - M)*invS;
    A4.w = __expf(-E4.w*invtau - M)*invS;
    __stcs((float4*)(out + (size_t)b*HW) + p4, A4);
}

// ---------------- launch ----------------
extern "C" void kernel_launch(void* const* d_in, const int* in_sizes, int n_in,
                              void* d_out, int out_size){
    const float* img    = (const float*)d_in[0];
    const float* cal_a  = (const float*)d_in[1];
    const float* cal_b  = (const float*)d_in[2];
    const float* alpha  = (const float*)d_in[3];
    const float* tau_p  = (const float*)d_in[4];
    float* out = (float*)d_out;
    (void)in_sizes; (void)n_in; (void)out_size;

    k_gray_hist<<<dim3(HW/(256*4), BB, 1), 256>>>(img);
    k_otsu_params<<<BB, 32>>>(cal_a, cal_b, alpha, tau_p);
    k_morph<<<dim3(HH/TR, BB, 1), MT>>>();
    k_fused<<<dim3(16, 16, BB), dim3(16, 16, 1)>>>(out);
    k_A<<<dim3(HW/(512*4), BB, 1), 512>>>(out);
}